// round 6
// baseline (speedup 1.0000x reference)
#include <cuda_runtime.h>
#include <math.h>

#define HID     2048
#define KVD     512
#define HEADS   16
#define GROUPS  4
#define HDIM    128
#define BATCH   2
#define SEQ     2048
#define MROWS   (BATCH*SEQ)   // 4096

// ---------------- scratch (no cudaMalloc allowed) ----------------
__device__ float g_Q[(size_t)MROWS * HID];   // 32 MB
__device__ float g_K[(size_t)MROWS * KVD];   //  8 MB
__device__ float g_V[(size_t)MROWS * KVD];   //  8 MB
__device__ float g_O[(size_t)MROWS * HID];   // 32 MB

// ---------------- helpers ----------------
__device__ __forceinline__ unsigned f2tf(float x) {
    unsigned u;
    asm("cvt.rna.tf32.f32 %0, %1;" : "=r"(u) : "f"(x));
    return u;
}
__device__ __forceinline__ float tfs(float x) { return __uint_as_float(f2tf(x)); }
__device__ __forceinline__ unsigned uf(float x) { return __float_as_uint(x); }

__device__ __forceinline__ float4 tf4(float4 v) {
    return make_float4(tfs(v.x), tfs(v.y), tfs(v.z), tfs(v.w));
}

__device__ __forceinline__ void mma_tf32(float c[4], const unsigned a[4], const unsigned b[2]) {
    asm volatile(
        "mma.sync.aligned.m16n8k8.row.col.f32.tf32.tf32.f32 "
        "{%0,%1,%2,%3},{%4,%5,%6,%7},{%8,%9},{%0,%1,%2,%3};\n"
        : "+f"(c[0]), "+f"(c[1]), "+f"(c[2]), "+f"(c[3])
        : "r"(a[0]), "r"(a[1]), "r"(a[2]), "r"(a[3]), "r"(b[0]), "r"(b[1]));
}

__device__ __forceinline__ void cp_async16(void* smem, const void* gmem) {
    unsigned sa = (unsigned)__cvta_generic_to_shared(smem);
    asm volatile("cp.async.cg.shared.global [%0], [%1], 16;\n" :: "r"(sa), "l"(gmem));
}
#define CP_COMMIT asm volatile("cp.async.commit_group;\n")
#define CP_WAIT0  asm volatile("cp.async.wait_group 0;\n")

// ================= GEMM (tf32 tensor cores): C[M,N] = A[M,K]@W[K,N] + bias =================
// 128x128x32 tile, 256 threads = 8 warps (4x2), warp tile 32x64, 2-stage cp.async.
// After each tile lands, a single in-place pass converts it to tf32 (cvt once
// per element instead of once per consuming warp).
// As[st][128][36]: bank(36r+k) = 4r+k mod 32 -> conflict-free A-frag reads.
// Bs[st][32][136]: bank(136k+n) = 8k+n mod 32 -> conflict-free B-frag reads.
#define GBK 32
#define G_AS (128*36)
#define G_BS (32*136)
#define GSMEM ((2*G_AS + 2*G_BS) * 4)   // 71680 B

__global__ __launch_bounds__(256, 2) void gemm_mma(
    const float* __restrict__ A, const float* __restrict__ W,
    const float* __restrict__ bias, float* __restrict__ C,
    int M, int N, int K)
{
    extern __shared__ float gsm[];
    float (*As)[128][36]  = (float(*)[128][36])gsm;
    float (*Bs)[32][136]  = (float(*)[32][136])(gsm + 2 * G_AS);

    const int tid = threadIdx.x;
    const int lane = tid & 31, wid = tid >> 5;
    const int gid = lane >> 2, tig = lane & 3;
    const int wm = wid >> 1, wn = wid & 1;
    const int bm = blockIdx.y * 128, bn = blockIdx.x * 128;

    float acc[2][8][4];
#pragma unroll
    for (int i = 0; i < 2; i++)
#pragma unroll
        for (int j = 0; j < 8; j++)
#pragma unroll
            for (int v = 0; v < 4; v++) acc[i][j][v] = 0.f;

    const int T = K / GBK;

    // stage loader: A tile 128x32 (1024 16B chunks), B tile 32x128 (1024 chunks)
    auto load_stage = [&](int st, int t) {
        const int k0 = t * GBK;
#pragma unroll
        for (int u = 0; u < 4; u++) {
            int id = tid + u * 256;
            int ra = id >> 3, ca = id & 7;           // A: 8 chunks per row
            cp_async16(&As[st][ra][ca * 4],
                       A + (size_t)(bm + ra) * K + k0 + ca * 4);
            int rb = id >> 5, cb = id & 31;          // B: 32 chunks per row
            cp_async16(&Bs[st][rb][cb * 4],
                       W + (size_t)(k0 + rb) * N + bn + cb * 4);
        }
    };

    // in-place tf32 conversion of a landed stage
    auto convert_stage = [&](int st) {
#pragma unroll
        for (int u = 0; u < 4; u++) {
            int id = tid + u * 256;
            int ra = id >> 3, ca = id & 7;
            float4* pa = (float4*)&As[st][ra][ca * 4];
            *pa = tf4(*pa);
            int rb = id >> 5, cb = id & 31;
            float4* pb = (float4*)&Bs[st][rb][cb * 4];
            *pb = tf4(*pb);
        }
    };

    load_stage(0, 0);
    CP_COMMIT;

    for (int t = 0; t < T; t++) {
        const int st = t & 1;
        CP_WAIT0;
        __syncthreads();          // tile t landed; prev compute done with buffer st^1
        if (t + 1 < T) {
            load_stage(st ^ 1, t + 1);
            CP_COMMIT;
        }
        convert_stage(st);
        __syncthreads();          // converted tile visible to all warps

#pragma unroll
        for (int kk = 0; kk < GBK; kk += 8) {
            unsigned a[2][4];
#pragma unroll
            for (int mt = 0; mt < 2; mt++) {
                int r = wm * 32 + mt * 16 + gid;
                a[mt][0] = uf(As[st][r][kk + tig]);
                a[mt][1] = uf(As[st][r + 8][kk + tig]);
                a[mt][2] = uf(As[st][r][kk + tig + 4]);
                a[mt][3] = uf(As[st][r + 8][kk + tig + 4]);
            }
#pragma unroll
            for (int nt = 0; nt < 8; nt++) {
                unsigned bf[2];
                int c = wn * 64 + nt * 8 + gid;
                bf[0] = uf(Bs[st][kk + tig][c]);
                bf[1] = uf(Bs[st][kk + tig + 4][c]);
                mma_tf32(acc[0][nt], a[0], bf);
                mma_tf32(acc[1][nt], a[1], bf);
            }
        }
    }

    // epilogue
#pragma unroll
    for (int mt = 0; mt < 2; mt++) {
        int r0 = bm + wm * 32 + mt * 16 + gid;
#pragma unroll
        for (int nt = 0; nt < 8; nt++) {
            int c = bn + wn * 64 + nt * 8 + 2 * tig;
            float bx = bias[c], by = bias[c + 1];
            float2 v0 = make_float2(acc[mt][nt][0] + bx, acc[mt][nt][1] + by);
            float2 v1 = make_float2(acc[mt][nt][2] + bx, acc[mt][nt][3] + by);
            *(float2*)&C[(size_t)r0 * N + c] = v0;
            *(float2*)&C[(size_t)(r0 + 8) * N + c] = v1;
        }
    }
}

// ================= Flash attention on tensor cores =================
// 256 threads = 8 warps. Q tile 128x128 (warp owns 16 rows), K/V tiles 32x128,
// double-buffered via cp.async, converted to tf32 in-place once per tile.
#define AQP 132
#define AKP 132
#define AVP 136
#define APP 36
#define OQ_  0
#define OKs  (128*AQP)                 // 16896
#define OVs  (OKs + 2*32*AKP)          // +8448
#define OPs  (OVs + 2*32*AVP)          // +8704
#define OMs  (OPs + 128*APP)           // +4608
#define ASMEM ((OMs + 2*32) * 4)       // 154880 B

__global__ __launch_bounds__(256, 1) void attn_mma(const int* __restrict__ mask)
{
    extern __shared__ float sm[];
    float (*Qs)[AQP]     = (float(*)[AQP])(sm + OQ_);
    float (*Ks)[32][AKP] = (float(*)[32][AKP])(sm + OKs);
    float (*Vs)[32][AVP] = (float(*)[32][AVP])(sm + OVs);
    float (*Ps)[APP]     = (float(*)[APP])(sm + OPs);
    int (*Ms)[32]        = (int(*)[32])(sm + OMs);

    const int tid = threadIdx.x;
    const int w = tid >> 5, lane = tid & 31;
    const int gid = lane >> 2, tig = lane & 3;
    const int qt = blockIdx.x, h = blockIdx.y, b = blockIdx.z;
    const int g = h % GROUPS;
    const int q0 = qt * 128;

    const float scale = 0.08838834764831845f;  // 1/sqrt(128)
    const float* Qg = g_Q + (size_t)(b * SEQ + q0) * HID + h * HDIM;
    const float* Kg0 = g_K + (size_t)(b * SEQ) * KVD + g * HDIM;
    const float* Vg0 = g_V + (size_t)(b * SEQ) * KVD + g * HDIM;
    const int*   Mg0 = mask + b * SEQ;

    auto issue_kv = [&](int st, int kt) {
        const int k0 = kt * 32;
#pragma unroll
        for (int u = 0; u < 4; u++) {
            int id = tid + u * 256;
            int r = id >> 5, c4 = id & 31;
            cp_async16(&Ks[st][r][c4 * 4], Kg0 + (size_t)(k0 + r) * KVD + c4 * 4);
            cp_async16(&Vs[st][r][c4 * 4], Vg0 + (size_t)(k0 + r) * KVD + c4 * 4);
        }
        if (tid < 8) cp_async16(&Ms[st][tid * 4], Mg0 + k0 + tid * 4);
    };

    auto convert_kv = [&](int st) {
#pragma unroll
        for (int u = 0; u < 4; u++) {
            int id = tid + u * 256;
            int r = id >> 5, c4 = id & 31;
            float4* pk = (float4*)&Ks[st][r][c4 * 4];
            *pk = tf4(*pk);
            float4* pv = (float4*)&Vs[st][r][c4 * 4];
            *pv = tf4(*pv);
        }
    };

    // prologue: start kt=0 loads, then fill Q tile (pre-scaled + tf32-rounded)
    issue_kv(0, 0);
    CP_COMMIT;

#pragma unroll
    for (int u = 0; u < 16; u++) {
        int idx = tid + u * 256;
        int r = idx >> 5, c4 = idx & 31;
        float4 v = *(const float4*)(Qg + (size_t)r * HID + c4 * 4);
        float4 o = make_float4(tfs(v.x * scale), tfs(v.y * scale),
                               tfs(v.z * scale), tfs(v.w * scale));
        *(float4*)&Qs[r][c4 * 4] = o;
    }

    float m_run[2] = {-1e30f, -1e30f};
    float l_run[2] = {0.f, 0.f};
    float o_acc[16][4];
#pragma unroll
    for (int nt = 0; nt < 16; nt++)
#pragma unroll
        for (int v = 0; v < 4; v++) o_acc[nt][v] = 0.f;

    const int r = w * 16 + gid;   // warp's base row

    for (int kt = 0; kt < SEQ / 32; kt++) {
        const int st = kt & 1;
        CP_WAIT0;
        __syncthreads();          // kt tile landed; all warps done with kt-1 buffers
        if (kt + 1 < SEQ / 32) {
            issue_kv(st ^ 1, kt + 1);
            CP_COMMIT;
        }
        convert_kv(st);
        __syncthreads();          // converted K/V visible to all warps

        // ---- S = Q @ K^T  (warp: 16 rows x 32 keys) ----
        float s[4][4];
#pragma unroll
        for (int nt = 0; nt < 4; nt++)
#pragma unroll
            for (int v = 0; v < 4; v++) s[nt][v] = 0.f;

#pragma unroll
        for (int ks = 0; ks < 16; ks++) {
            const int kk = ks * 8;
            unsigned qa[4];
            qa[0] = uf(Qs[r][kk + tig]);
            qa[1] = uf(Qs[r + 8][kk + tig]);
            qa[2] = uf(Qs[r][kk + tig + 4]);
            qa[3] = uf(Qs[r + 8][kk + tig + 4]);
#pragma unroll
            for (int nt = 0; nt < 4; nt++) {
                unsigned kb[2];
                kb[0] = uf(Ks[st][nt * 8 + gid][kk + tig]);
                kb[1] = uf(Ks[st][nt * 8 + gid][kk + tig + 4]);
                mma_tf32(s[nt], qa, kb);
            }
        }

        // ---- mask ----
#pragma unroll
        for (int nt = 0; nt < 4; nt++) {
            int c = nt * 8 + 2 * tig;
            if (Ms[st][c] == 0)     { s[nt][0] = -1e30f; s[nt][2] = -1e30f; }
            if (Ms[st][c + 1] == 0) { s[nt][1] = -1e30f; s[nt][3] = -1e30f; }
        }

        // ---- online softmax (row halves: gid and gid+8) ----
#pragma unroll
        for (int hh = 0; hh < 2; hh++) {
            float mx = -1e30f;
#pragma unroll
            for (int nt = 0; nt < 4; nt++)
                mx = fmaxf(mx, fmaxf(s[nt][2 * hh], s[nt][2 * hh + 1]));
            mx = fmaxf(mx, __shfl_xor_sync(0xffffffffu, mx, 1));
            mx = fmaxf(mx, __shfl_xor_sync(0xffffffffu, mx, 2));
            float mnew = fmaxf(m_run[hh], mx);
            float corr = __expf(m_run[hh] - mnew);
            float sum = 0.f;
#pragma unroll
            for (int nt = 0; nt < 4; nt++) {
                float p0 = __expf(s[nt][2 * hh] - mnew);
                float p1 = __expf(s[nt][2 * hh + 1] - mnew);
                s[nt][2 * hh] = p0; s[nt][2 * hh + 1] = p1;
                sum += p0 + p1;
            }
            sum += __shfl_xor_sync(0xffffffffu, sum, 1);
            sum += __shfl_xor_sync(0xffffffffu, sum, 2);
            l_run[hh] = l_run[hh] * corr + sum;
            if (mnew > m_run[hh]) {        // corr < 1: rescale needed (exact skip otherwise)
                m_run[hh] = mnew;
#pragma unroll
                for (int nt = 0; nt < 16; nt++) {
                    o_acc[nt][2 * hh] *= corr;
                    o_acc[nt][2 * hh + 1] *= corr;
                }
            }
        }

        // ---- store P (own warp rows only) ----
#pragma unroll
        for (int nt = 0; nt < 4; nt++) {
            int c = nt * 8 + 2 * tig;
            float2 p0 = make_float2(tfs(s[nt][0]), tfs(s[nt][1]));
            float2 p1 = make_float2(tfs(s[nt][2]), tfs(s[nt][3]));
            *(float2*)&Ps[r][c] = p0;
            *(float2*)&Ps[r + 8][c] = p1;
        }
        __syncwarp();

        // ---- O += P @ V  (warp: 16 rows x 128 dims) ----
#pragma unroll
        for (int ks = 0; ks < 4; ks++) {
            const int kk = ks * 8;
            unsigned pa[4];
            pa[0] = uf(Ps[r][kk + tig]);
            pa[1] = uf(Ps[r + 8][kk + tig]);
            pa[2] = uf(Ps[r][kk + tig + 4]);
            pa[3] = uf(Ps[r + 8][kk + tig + 4]);
#pragma unroll
            for (int nt = 0; nt < 16; nt++) {
                unsigned vb[2];
                vb[0] = uf(Vs[st][kk + tig][nt * 8 + gid]);
                vb[1] = uf(Vs[st][kk + tig + 4][nt * 8 + gid]);
                mma_tf32(o_acc[nt], pa, vb);
            }
        }
    }

    // ---- epilogue: O /= l ----
    float* Og = g_O + (size_t)(b * SEQ + q0) * HID + h * HDIM;
    const float i0 = 1.f / l_run[0], i1 = 1.f / l_run[1];
#pragma unroll
    for (int nt = 0; nt < 16; nt++) {
        int c = nt * 8 + 2 * tig;
        float2 v0 = make_float2(o_acc[nt][0] * i0, o_acc[nt][1] * i0);
        float2 v1 = make_float2(o_acc[nt][2] * i1, o_acc[nt][3] * i1);
        *(float2*)&Og[(size_t)r * HID + c] = v0;
        *(float2*)&Og[(size_t)(r + 8) * HID + c] = v1;
    }
}

// ================= launch =================
extern "C" void kernel_launch(void* const* d_in, const int* in_sizes, int n_in,
                              void* d_out, int out_size)
{
    const float* X    = (const float*)d_in[0];
    const int*   mask = (const int*)  d_in[1];
    const float* Wq   = (const float*)d_in[2];
    const float* bq   = (const float*)d_in[3];
    const float* Wk   = (const float*)d_in[4];
    const float* bk   = (const float*)d_in[5];
    const float* Wv   = (const float*)d_in[6];
    const float* bv   = (const float*)d_in[7];
    const float* Wo   = (const float*)d_in[8];
    const float* bo   = (const float*)d_in[9];
    float* out = (float*)d_out;

    float *Qp, *Kp, *Vp, *Op;
    cudaGetSymbolAddress((void**)&Qp, g_Q);
    cudaGetSymbolAddress((void**)&Kp, g_K);
    cudaGetSymbolAddress((void**)&Vp, g_V);
    cudaGetSymbolAddress((void**)&Op, g_O);

    cudaFuncSetAttribute(gemm_mma,
                         cudaFuncAttributeMaxDynamicSharedMemorySize, GSMEM);
    cudaFuncSetAttribute(attn_mma,
                         cudaFuncAttributeMaxDynamicSharedMemorySize, ASMEM);

    dim3 blk(256);
    gemm_mma<<<dim3(HID / 128, MROWS / 128), blk, GSMEM>>>(X, Wq, bq, Qp, MROWS, HID, HID);
    gemm_mma<<<dim3(KVD / 128, MROWS / 128), blk, GSMEM>>>(X, Wk, bk, Kp, MROWS, KVD, HID);
    gemm_mma<<<dim3(KVD / 128, MROWS / 128), blk, GSMEM>>>(X, Wv, bv, Vp, MROWS, KVD, HID);

    attn_mma<<<dim3(SEQ / 128, HEADS, BATCH), blk, ASMEM>>>(mask);

    gemm_mma<<<dim3(HID / 128, MROWS / 128), blk, GSMEM>>>(Op, Wo, bo, out, MROWS, HID, HID);
}

// round 7
// speedup vs baseline: 1.2119x; 1.2119x over previous
#include <cuda_runtime.h>
#include <math.h>

#define HID     2048
#define KVD     512
#define HEADS   16
#define GROUPS  4
#define HDIM    128
#define BATCH   2
#define SEQ     2048
#define MROWS   (BATCH*SEQ)   // 4096

// ---------------- scratch (no cudaMalloc allowed) ----------------
__device__ float g_Q[(size_t)MROWS * HID];    // 32 MB (tf32-rounded at GEMM epilogue)
__device__ float g_K[(size_t)MROWS * KVD];    //  8 MB (tf32-rounded)
__device__ float g_V[(size_t)MROWS * KVD];    //  8 MB (tf32-rounded)
__device__ float g_O[(size_t)MROWS * HID];    // 32 MB (tf32-rounded at attn epilogue)
__device__ float g_Xt[(size_t)MROWS * HID];   // 32 MB tf32 copy of X
__device__ float g_Wqt[(size_t)HID * HID];    // 16 MB
__device__ float g_Wkt[(size_t)HID * KVD];    //  4 MB
__device__ float g_Wvt[(size_t)HID * KVD];    //  4 MB
__device__ float g_Wot[(size_t)HID * HID];    // 16 MB

// ---------------- helpers ----------------
__device__ __forceinline__ unsigned f2tf(float x) {
    unsigned u;
    asm("cvt.rna.tf32.f32 %0, %1;" : "=r"(u) : "f"(x));
    return u;
}
__device__ __forceinline__ float tfs(float x) { return __uint_as_float(f2tf(x)); }
__device__ __forceinline__ unsigned uf(float x) { return __float_as_uint(x); }

__device__ __forceinline__ void mma_tf32(float c[4], const unsigned a[4], const unsigned b[2]) {
    asm volatile(
        "mma.sync.aligned.m16n8k8.row.col.f32.tf32.tf32.f32 "
        "{%0,%1,%2,%3},{%4,%5,%6,%7},{%8,%9},{%0,%1,%2,%3};\n"
        : "+f"(c[0]), "+f"(c[1]), "+f"(c[2]), "+f"(c[3])
        : "r"(a[0]), "r"(a[1]), "r"(a[2]), "r"(a[3]), "r"(b[0]), "r"(b[1]));
}

__device__ __forceinline__ void cp_async16(void* smem, const void* gmem) {
    unsigned sa = (unsigned)__cvta_generic_to_shared(smem);
    asm volatile("cp.async.cg.shared.global [%0], [%1], 16;\n" :: "r"(sa), "l"(gmem));
}
#define CP_COMMIT asm volatile("cp.async.commit_group;\n")
#define CP_WAIT0  asm volatile("cp.async.wait_group 0;\n")

// ================= tf32 pre-cast: out[i] = tf32(in[i]) =================
__global__ __launch_bounds__(256) void tf32_cast(const float* __restrict__ in,
                                                 float* __restrict__ out, int n4)
{
    int i = blockIdx.x * 256 + threadIdx.x;
    if (i < n4) {
        float4 v = ((const float4*)in)[i];
        float4 o = make_float4(tfs(v.x), tfs(v.y), tfs(v.z), tfs(v.w));
        ((float4*)out)[i] = o;
    }
}

// ================= GEMM (tf32 tensor cores): C[M,N] = A[M,K]@W[K,N] + bias ===========
// Operands pre-rounded to tf32 -> no cvt anywhere in the inner loop.
// 128x128x32 tile, 256 threads = 8 warps (4x2), warp tile 32x64, 2-stage cp.async.
// As[st][128][36]: bank(36r+k) = 4r+k mod 32 -> conflict-free A-frag reads.
// Bs[st][32][136]: bank(136k+n) = 8k+n mod 32 -> conflict-free B-frag reads.
#define GBK 32
#define G_AS (128*36)
#define G_BS (32*136)
#define GSMEM ((2*G_AS + 2*G_BS) * 4)   // 71680 B

template<int WRITE_TF>
__global__ __launch_bounds__(256, 2) void gemm_mma(
    const float* __restrict__ A, const float* __restrict__ W,
    const float* __restrict__ bias, float* __restrict__ C,
    int M, int N, int K)
{
    extern __shared__ float gsm[];
    float (*As)[128][36]  = (float(*)[128][36])gsm;
    float (*Bs)[32][136]  = (float(*)[32][136])(gsm + 2 * G_AS);

    const int tid = threadIdx.x;
    const int lane = tid & 31, wid = tid >> 5;
    const int gid = lane >> 2, tig = lane & 3;
    const int wm = wid >> 1, wn = wid & 1;
    const int bm = blockIdx.y * 128, bn = blockIdx.x * 128;

    float acc[2][8][4];
#pragma unroll
    for (int i = 0; i < 2; i++)
#pragma unroll
        for (int j = 0; j < 8; j++)
#pragma unroll
            for (int v = 0; v < 4; v++) acc[i][j][v] = 0.f;

    const int T = K / GBK;

    auto load_stage = [&](int st, int t) {
        const int k0 = t * GBK;
#pragma unroll
        for (int u = 0; u < 4; u++) {
            int id = tid + u * 256;
            int ra = id >> 3, ca = id & 7;           // A: 8 chunks per row
            cp_async16(&As[st][ra][ca * 4],
                       A + (size_t)(bm + ra) * K + k0 + ca * 4);
            int rb = id >> 5, cb = id & 31;          // B: 32 chunks per row
            cp_async16(&Bs[st][rb][cb * 4],
                       W + (size_t)(k0 + rb) * N + bn + cb * 4);
        }
    };

    load_stage(0, 0);
    CP_COMMIT;

    for (int t = 0; t < T; t++) {
        const int st = t & 1;
        CP_WAIT0;
        __syncthreads();          // tile t landed; prev compute done with buffer st^1
        if (t + 1 < T) {
            load_stage(st ^ 1, t + 1);
            CP_COMMIT;
        }

#pragma unroll
        for (int kk = 0; kk < GBK; kk += 8) {
            unsigned a[2][4];
#pragma unroll
            for (int mt = 0; mt < 2; mt++) {
                int r = wm * 32 + mt * 16 + gid;
                a[mt][0] = uf(As[st][r][kk + tig]);
                a[mt][1] = uf(As[st][r + 8][kk + tig]);
                a[mt][2] = uf(As[st][r][kk + tig + 4]);
                a[mt][3] = uf(As[st][r + 8][kk + tig + 4]);
            }
#pragma unroll
            for (int nt = 0; nt < 8; nt++) {
                unsigned bf[2];
                int c = wn * 64 + nt * 8 + gid;
                bf[0] = uf(Bs[st][kk + tig][c]);
                bf[1] = uf(Bs[st][kk + tig + 4][c]);
                mma_tf32(acc[0][nt], a[0], bf);
                mma_tf32(acc[1][nt], a[1], bf);
            }
        }
    }

    // epilogue (optionally writes tf32-rounded values for downstream consumers)
#pragma unroll
    for (int mt = 0; mt < 2; mt++) {
        int r0 = bm + wm * 32 + mt * 16 + gid;
#pragma unroll
        for (int nt = 0; nt < 8; nt++) {
            int c = bn + wn * 64 + nt * 8 + 2 * tig;
            float bx = bias[c], by = bias[c + 1];
            float2 v0, v1;
            if (WRITE_TF) {
                v0 = make_float2(tfs(acc[mt][nt][0] + bx), tfs(acc[mt][nt][1] + by));
                v1 = make_float2(tfs(acc[mt][nt][2] + bx), tfs(acc[mt][nt][3] + by));
            } else {
                v0 = make_float2(acc[mt][nt][0] + bx, acc[mt][nt][1] + by);
                v1 = make_float2(acc[mt][nt][2] + bx, acc[mt][nt][3] + by);
            }
            *(float2*)&C[(size_t)r0 * N + c] = v0;
            *(float2*)&C[(size_t)(r0 + 8) * N + c] = v1;
        }
    }
}

// ================= Flash attention on tensor cores =================
// 256 threads = 8 warps. Q tile 128x128 (warp owns 16 rows), K/V tiles 32x128,
// double-buffered via cp.async. K/V/Q arrive pre-rounded -> no cvt in the loop.
#define AQP 132
#define AKP 132
#define AVP 136
#define APP 36
#define OQ_  0
#define OKs  (128*AQP)                 // 16896
#define OVs  (OKs + 2*32*AKP)          // +8448
#define OPs  (OVs + 2*32*AVP)          // +8704
#define OMs  (OPs + 128*APP)           // +4608
#define ASMEM ((OMs + 2*32) * 4)       // 154880 B

__global__ __launch_bounds__(256, 1) void attn_mma(const int* __restrict__ mask)
{
    extern __shared__ float sm[];
    float (*Qs)[AQP]     = (float(*)[AQP])(sm + OQ_);
    float (*Ks)[32][AKP] = (float(*)[32][AKP])(sm + OKs);
    float (*Vs)[32][AVP] = (float(*)[32][AVP])(sm + OVs);
    float (*Ps)[APP]     = (float(*)[APP])(sm + OPs);
    int (*Ms)[32]        = (int(*)[32])(sm + OMs);

    const int tid = threadIdx.x;
    const int w = tid >> 5, lane = tid & 31;
    const int gid = lane >> 2, tig = lane & 3;
    const int qt = blockIdx.x, h = blockIdx.y, b = blockIdx.z;
    const int g = h % GROUPS;
    const int q0 = qt * 128;

    const float scale = 0.08838834764831845f;  // 1/sqrt(128)
    const float* Qg = g_Q + (size_t)(b * SEQ + q0) * HID + h * HDIM;
    const float* Kg0 = g_K + (size_t)(b * SEQ) * KVD + g * HDIM;
    const float* Vg0 = g_V + (size_t)(b * SEQ) * KVD + g * HDIM;
    const int*   Mg0 = mask + b * SEQ;

    auto issue_kv = [&](int st, int kt) {
        const int k0 = kt * 32;
#pragma unroll
        for (int u = 0; u < 4; u++) {
            int id = tid + u * 256;
            int r = id >> 5, c4 = id & 31;
            cp_async16(&Ks[st][r][c4 * 4], Kg0 + (size_t)(k0 + r) * KVD + c4 * 4);
            cp_async16(&Vs[st][r][c4 * 4], Vg0 + (size_t)(k0 + r) * KVD + c4 * 4);
        }
        if (tid < 8) cp_async16(&Ms[st][tid * 4], Mg0 + k0 + tid * 4);
    };

    // prologue: start kt=0 loads, then fill Q tile (scale + re-round, once per element)
    issue_kv(0, 0);
    CP_COMMIT;

#pragma unroll
    for (int u = 0; u < 16; u++) {
        int idx = tid + u * 256;
        int r = idx >> 5, c4 = idx & 31;
        float4 v = *(const float4*)(Qg + (size_t)r * HID + c4 * 4);
        float4 o = make_float4(tfs(v.x * scale), tfs(v.y * scale),
                               tfs(v.z * scale), tfs(v.w * scale));
        *(float4*)&Qs[r][c4 * 4] = o;
    }

    float m_run[2] = {-1e30f, -1e30f};
    float l_run[2] = {0.f, 0.f};
    float o_acc[16][4];
#pragma unroll
    for (int nt = 0; nt < 16; nt++)
#pragma unroll
        for (int v = 0; v < 4; v++) o_acc[nt][v] = 0.f;

    const int r = w * 16 + gid;   // warp's base row

    for (int kt = 0; kt < SEQ / 32; kt++) {
        const int st = kt & 1;
        CP_WAIT0;
        __syncthreads();          // kt tile landed; all warps done with kt-1 buffers
        if (kt + 1 < SEQ / 32) {
            issue_kv(st ^ 1, kt + 1);
            CP_COMMIT;
        }

        // ---- S = Q @ K^T  (warp: 16 rows x 32 keys) ----
        float s[4][4];
#pragma unroll
        for (int nt = 0; nt < 4; nt++)
#pragma unroll
            for (int v = 0; v < 4; v++) s[nt][v] = 0.f;

#pragma unroll
        for (int ks = 0; ks < 16; ks++) {
            const int kk = ks * 8;
            unsigned qa[4];
            qa[0] = uf(Qs[r][kk + tig]);
            qa[1] = uf(Qs[r + 8][kk + tig]);
            qa[2] = uf(Qs[r][kk + tig + 4]);
            qa[3] = uf(Qs[r + 8][kk + tig + 4]);
#pragma unroll
            for (int nt = 0; nt < 4; nt++) {
                unsigned kb[2];
                kb[0] = uf(Ks[st][nt * 8 + gid][kk + tig]);
                kb[1] = uf(Ks[st][nt * 8 + gid][kk + tig + 4]);
                mma_tf32(s[nt], qa, kb);
            }
        }

        // ---- mask ----
#pragma unroll
        for (int nt = 0; nt < 4; nt++) {
            int c = nt * 8 + 2 * tig;
            if (Ms[st][c] == 0)     { s[nt][0] = -1e30f; s[nt][2] = -1e30f; }
            if (Ms[st][c + 1] == 0) { s[nt][1] = -1e30f; s[nt][3] = -1e30f; }
        }

        // ---- online softmax (row halves: gid and gid+8) ----
#pragma unroll
        for (int hh = 0; hh < 2; hh++) {
            float mx = -1e30f;
#pragma unroll
            for (int nt = 0; nt < 4; nt++)
                mx = fmaxf(mx, fmaxf(s[nt][2 * hh], s[nt][2 * hh + 1]));
            mx = fmaxf(mx, __shfl_xor_sync(0xffffffffu, mx, 1));
            mx = fmaxf(mx, __shfl_xor_sync(0xffffffffu, mx, 2));
            float mnew = fmaxf(m_run[hh], mx);
            float corr = __expf(m_run[hh] - mnew);
            float sum = 0.f;
#pragma unroll
            for (int nt = 0; nt < 4; nt++) {
                float p0 = __expf(s[nt][2 * hh] - mnew);
                float p1 = __expf(s[nt][2 * hh + 1] - mnew);
                s[nt][2 * hh] = p0; s[nt][2 * hh + 1] = p1;
                sum += p0 + p1;
            }
            sum += __shfl_xor_sync(0xffffffffu, sum, 1);
            sum += __shfl_xor_sync(0xffffffffu, sum, 2);
            l_run[hh] = l_run[hh] * corr + sum;
            if (mnew > m_run[hh]) {        // corr < 1: rescale needed (exact skip otherwise)
                m_run[hh] = mnew;
#pragma unroll
                for (int nt = 0; nt < 16; nt++) {
                    o_acc[nt][2 * hh] *= corr;
                    o_acc[nt][2 * hh + 1] *= corr;
                }
            }
        }

        // ---- store P (own warp rows only) ----
#pragma unroll
        for (int nt = 0; nt < 4; nt++) {
            int c = nt * 8 + 2 * tig;
            float2 p0 = make_float2(tfs(s[nt][0]), tfs(s[nt][1]));
            float2 p1 = make_float2(tfs(s[nt][2]), tfs(s[nt][3]));
            *(float2*)&Ps[r][c] = p0;
            *(float2*)&Ps[r + 8][c] = p1;
        }
        __syncwarp();

        // ---- O += P @ V  (warp: 16 rows x 128 dims) ----
#pragma unroll
        for (int ks = 0; ks < 4; ks++) {
            const int kk = ks * 8;
            unsigned pa[4];
            pa[0] = uf(Ps[r][kk + tig]);
            pa[1] = uf(Ps[r + 8][kk + tig]);
            pa[2] = uf(Ps[r][kk + tig + 4]);
            pa[3] = uf(Ps[r + 8][kk + tig + 4]);
#pragma unroll
            for (int nt = 0; nt < 16; nt++) {
                unsigned vb[2];
                vb[0] = uf(Vs[st][kk + tig][nt * 8 + gid]);
                vb[1] = uf(Vs[st][kk + tig + 4][nt * 8 + gid]);
                mma_tf32(o_acc[nt], pa, vb);
            }
        }
    }

    // ---- epilogue: O /= l, tf32-rounded for the output-projection GEMM ----
    float* Og = g_O + (size_t)(b * SEQ + q0) * HID + h * HDIM;
    const float i0 = 1.f / l_run[0], i1 = 1.f / l_run[1];
#pragma unroll
    for (int nt = 0; nt < 16; nt++) {
        int c = nt * 8 + 2 * tig;
        float2 v0 = make_float2(tfs(o_acc[nt][0] * i0), tfs(o_acc[nt][1] * i0));
        float2 v1 = make_float2(tfs(o_acc[nt][2] * i1), tfs(o_acc[nt][3] * i1));
        *(float2*)&Og[(size_t)r * HID + c] = v0;
        *(float2*)&Og[(size_t)(r + 8) * HID + c] = v1;
    }
}

// ================= launch =================
extern "C" void kernel_launch(void* const* d_in, const int* in_sizes, int n_in,
                              void* d_out, int out_size)
{
    const float* X    = (const float*)d_in[0];
    const int*   mask = (const int*)  d_in[1];
    const float* Wq   = (const float*)d_in[2];
    const float* bq   = (const float*)d_in[3];
    const float* Wk   = (const float*)d_in[4];
    const float* bk   = (const float*)d_in[5];
    const float* Wv   = (const float*)d_in[6];
    const float* bv   = (const float*)d_in[7];
    const float* Wo   = (const float*)d_in[8];
    const float* bo   = (const float*)d_in[9];
    float* out = (float*)d_out;

    float *Qp, *Kp, *Vp, *Op, *Xt, *Wqt, *Wkt, *Wvt, *Wot;
    cudaGetSymbolAddress((void**)&Qp, g_Q);
    cudaGetSymbolAddress((void**)&Kp, g_K);
    cudaGetSymbolAddress((void**)&Vp, g_V);
    cudaGetSymbolAddress((void**)&Op, g_O);
    cudaGetSymbolAddress((void**)&Xt, g_Xt);
    cudaGetSymbolAddress((void**)&Wqt, g_Wqt);
    cudaGetSymbolAddress((void**)&Wkt, g_Wkt);
    cudaGetSymbolAddress((void**)&Wvt, g_Wvt);
    cudaGetSymbolAddress((void**)&Wot, g_Wot);

    cudaFuncSetAttribute(gemm_mma<0>,
                         cudaFuncAttributeMaxDynamicSharedMemorySize, GSMEM);
    cudaFuncSetAttribute(gemm_mma<1>,
                         cudaFuncAttributeMaxDynamicSharedMemorySize, GSMEM);
    cudaFuncSetAttribute(attn_mma,
                         cudaFuncAttributeMaxDynamicSharedMemorySize, ASMEM);

    // pre-round inputs to tf32 (each read many times downstream)
    {
        int nX  = MROWS * HID / 4, nWq = HID * HID / 4,
            nWk = HID * KVD / 4,  nWo = HID * HID / 4;
        tf32_cast<<<(nX  + 255) / 256, 256>>>(X,  Xt,  nX);
        tf32_cast<<<(nWq + 255) / 256, 256>>>(Wq, Wqt, nWq);
        tf32_cast<<<(nWk + 255) / 256, 256>>>(Wk, Wkt, nWk);
        tf32_cast<<<(nWk + 255) / 256, 256>>>(Wv, Wvt, nWk);
        tf32_cast<<<(nWo + 255) / 256, 256>>>(Wo, Wot, nWo);
    }

    dim3 blk(256);
    gemm_mma<1><<<dim3(HID / 128, MROWS / 128), blk, GSMEM>>>(Xt, Wqt, bq, Qp, MROWS, HID, HID);
    gemm_mma<1><<<dim3(KVD / 128, MROWS / 128), blk, GSMEM>>>(Xt, Wkt, bk, Kp, MROWS, KVD, HID);
    gemm_mma<1><<<dim3(KVD / 128, MROWS / 128), blk, GSMEM>>>(Xt, Wvt, bv, Vp, MROWS, KVD, HID);

    attn_mma<<<dim3(SEQ / 128, HEADS, BATCH), blk, ASMEM>>>(mask);

    gemm_mma<0><<<dim3(HID / 128, MROWS / 128), blk, GSMEM>>>(Op, Wot, bo, out, MROWS, HID, HID);
}